// round 2
// baseline (speedup 1.0000x reference)
#include <cuda_runtime.h>
#include <math.h>

// ---------------- problem constants ----------------
constexpr int NB     = 2;
constexpr int NC     = 256;     // channels (= QK)
constexpr int NHW    = 16384;   // H*W
constexpr int NS     = 256;     // superpixels
constexpr int NT     = 128;     // top-k
constexpr int NHEADS = 8;
constexpr int NDH    = 32;      // head dim
constexpr int MTOT   = 768;     // q(256) + k(256) + v(256)
constexpr float EPSV      = 1e-5f;
constexpr float ATT_SCALE = 0.17677669529663687f;  // 1/sqrt(32)

// ---------------- scratch (device globals; no allocations allowed) ----------
__device__ float g_xn [(size_t)NB * NC * NHW];          //  33.5 MB layernormed x
__device__ float g_yt [(size_t)NB * NHW * MTOT];        // 100.7 MB qkv, transposed (n-major)
__device__ float g_acc[(size_t)NB * NHW * NC];          //  33.5 MB output accumulator (n-major)
__device__ float g_sims[NB * NS * NT];
__device__ int   g_idx [NB * NS * NT];

// =====================================================================
// Kernel 1: LayerNorm over channel dim, per pixel.
// =====================================================================
__global__ void __launch_bounds__(256) ln_kernel(const float* __restrict__ x,
                                                 const float* __restrict__ w,
                                                 const float* __restrict__ bias) {
    int p = blockIdx.x * blockDim.x + threadIdx.x;   // 0 .. NB*NHW-1
    int b = p / NHW;
    int n = p - b * NHW;
    const float* xb = x + (size_t)b * NC * NHW + n;
    float s = 0.f, ss = 0.f;
#pragma unroll 8
    for (int c = 0; c < NC; c++) {
        float v = xb[(size_t)c * NHW];
        s += v; ss += v * v;
    }
    float mu  = s * (1.0f / NC);
    float var = ss * (1.0f / NC) - mu * mu;
    float inv = rsqrtf(var + EPSV);
    float* o = g_xn + (size_t)b * NC * NHW + n;
#pragma unroll 8
    for (int c = 0; c < NC; c++) {
        o[(size_t)c * NHW] = (xb[(size_t)c * NHW] - mu) * inv * w[c] + bias[c];
    }
}

// =====================================================================
// Kernel 2: exact top-128 (value,index) per affinity row via radix select.
// Order within the top-k doesn't matter (pipeline is permutation invariant);
// ties at the threshold broken toward lowest index (matches lax.top_k).
// =====================================================================
__device__ __forceinline__ unsigned f2k(float f) {
    unsigned u = __float_as_uint(f);
    return (u & 0x80000000u) ? ~u : (u | 0x80000000u);
}

__global__ void __launch_bounds__(256) topk_kernel(const float* __restrict__ aff) {
    const int row = blockIdx.x;                 // b*NS + s
    const float* a = aff + (size_t)row * NHW;

    __shared__ unsigned hist[256];
    __shared__ unsigned sh_digit, sh_rem;
    __shared__ int cnt_gt, eqcnt;
    __shared__ int eqlist[64];

    unsigned prefix = 0, prefmask = 0;
    unsigned rem = NT;

    for (int shift = 24; shift >= 0; shift -= 8) {
        for (int i = threadIdx.x; i < 256; i += blockDim.x) hist[i] = 0;
        __syncthreads();
        for (int i = threadIdx.x; i < NHW; i += blockDim.x) {
            unsigned key = f2k(a[i]);
            if ((key & prefmask) == prefix)
                atomicAdd(&hist[(key >> shift) & 255u], 1u);
        }
        __syncthreads();
        if (threadIdx.x == 0) {
            unsigned r = rem;
            int d = 255;
            for (; d > 0; d--) {
                unsigned c = hist[d];
                if (c >= r) break;
                r -= c;
            }
            sh_digit = (unsigned)d;
            sh_rem = r;
        }
        __syncthreads();
        prefix  |= (sh_digit << shift);
        prefmask |= (0xFFu << shift);
        rem = sh_rem;
        __syncthreads();
    }

    const unsigned thresh = prefix;   // key of the 128th-largest element
    if (threadIdx.x == 0) { cnt_gt = 0; eqcnt = 0; }
    __syncthreads();

    float* so = g_sims + (size_t)row * NT;
    int*   io = g_idx  + (size_t)row * NT;

    for (int i = threadIdx.x; i < NHW; i += blockDim.x) {
        float v = a[i];
        unsigned key = f2k(v);
        if (key > thresh) {
            int p = atomicAdd(&cnt_gt, 1);
            so[p] = v; io[p] = i;
        } else if (key == thresh) {
            int p = atomicAdd(&eqcnt, 1);
            if (p < 64) eqlist[p] = i;
        }
    }
    __syncthreads();
    if (threadIdx.x == 0) {
        int need = NT - cnt_gt;
        int m = eqcnt < 64 ? eqcnt : 64;
        // lowest-index tie-break: insertion sort (m is almost always 1)
        for (int i = 1; i < m; i++) {
            int key = eqlist[i]; int j = i - 1;
            while (j >= 0 && eqlist[j] > key) { eqlist[j + 1] = eqlist[j]; j--; }
            eqlist[j + 1] = key;
        }
        for (int r = 0; r < need && r < m; r++) {
            int i = eqlist[r];
            so[cnt_gt + r] = a[i];
            io[cnt_gt + r] = i;
        }
    }
}

// =====================================================================
// Kernel 3: QKV GEMM.  yt[b][n][m] = sum_c W[m][c] * xn[b][c][n]
// W = stacked [wq; wk; wv] (768 x 256).  Output n-major so the attention
// gather reads 128B contiguous per pixel.  v rows also seed g_acc.
// Tiling: BN=128(n) x BM=64(m) x BK=32, 256 threads, 8x4 per thread.
// =====================================================================
constexpr int GBN = 128, GBM = 64, GBK = 32;

__global__ void __launch_bounds__(256) gemm_kernel(const float* __restrict__ wq,
                                                   const float* __restrict__ wk,
                                                   const float* __restrict__ wv) {
    const int n0 = blockIdx.x * GBN;
    const int m0 = blockIdx.y * GBM;
    const int b  = blockIdx.z;

    __shared__ float Xs[GBK][GBN];       // 16 KB
    __shared__ float Ws[GBK][GBM + 4];   // ~8.7 KB, transposed, padded

    const int tid = threadIdx.x;
    const int tx = tid & 15;             // n-group: 16 groups x 8 n
    const int ty = tid >> 4;             // m-group: 16 groups x 4 m

    float acc[8][4];
#pragma unroll
    for (int i = 0; i < 8; i++)
#pragma unroll
        for (int j = 0; j < 4; j++) acc[i][j] = 0.f;

    for (int c0 = 0; c0 < NC; c0 += GBK) {
        // load X tile (coalesced)
#pragma unroll
        for (int r = 0; r < 4; r++) {
            int j  = tid + r * 256;
            int kk = j >> 5;
            int nc = j & 31;
            *(float4*)&Xs[kk][nc * 4] =
                *(const float4*)&g_xn[((size_t)b * NC + (c0 + kk)) * NHW + n0 + nc * 4];
        }
        // load W tile, transpose into smem
#pragma unroll
        for (int r = 0; r < 2; r++) {
            int j  = tid + r * 256;
            int m  = j >> 3;
            int kf = j & 7;
            int mg = m0 + m;
            const float* wr = (mg < 256) ? (wq + (size_t)mg * NC)
                            : (mg < 512) ? (wk + (size_t)(mg - 256) * NC)
                                         : (wv + (size_t)(mg - 512) * NC);
            float4 f = *(const float4*)(wr + c0 + kf * 4);
            Ws[kf * 4 + 0][m] = f.x;
            Ws[kf * 4 + 1][m] = f.y;
            Ws[kf * 4 + 2][m] = f.z;
            Ws[kf * 4 + 3][m] = f.w;
        }
        __syncthreads();

#pragma unroll
        for (int k = 0; k < GBK; k++) {
            float4 xa = *(float4*)&Xs[k][tx * 8];
            float4 xb = *(float4*)&Xs[k][tx * 8 + 4];
            float4 wf = *(float4*)&Ws[k][ty * 4];
            float xr[8] = {xa.x, xa.y, xa.z, xa.w, xb.x, xb.y, xb.z, xb.w};
            float wr[4] = {wf.x, wf.y, wf.z, wf.w};
#pragma unroll
            for (int in = 0; in < 8; in++)
#pragma unroll
                for (int im = 0; im < 4; im++)
                    acc[in][im] += xr[in] * wr[im];
        }
        __syncthreads();
    }

#pragma unroll
    for (int in = 0; in < 8; in++) {
        int n = n0 + tx * 8 + in;
        float4 o = make_float4(acc[in][0], acc[in][1], acc[in][2], acc[in][3]);
        size_t base = (size_t)b * NHW + n;
        *(float4*)&g_yt[base * MTOT + m0 + ty * 4] = o;
        if (m0 >= 512)  // v rows also initialize the scatter accumulator
            *(float4*)&g_acc[base * NC + (m0 - 512) + ty * 4] = o;
    }
}

// =====================================================================
// Kernel 4: attention per (s, head, b) tile.  128 threads = 1 thread per t.
// Gathered K and sims-weighted V staged in smem (broadcast reads),
// chunked online softmax, coalesced atomicAdd into g_acc (n-major).
// =====================================================================
constexpr int KSLD = NDH + 4;   // padded row stride (float4-aligned: 36*4=144B)

__global__ void __launch_bounds__(128) attn_kernel() {
    const int s = blockIdx.x, h = blockIdx.y, b = blockIdx.z;
    const int t = threadIdx.x;

    __shared__ float ks[NT][KSLD];   // K rows; reused as output staging
    __shared__ float vs[NT][KSLD];   // sims-weighted V rows
    __shared__ int   idxv[NT];

    const int gi  = (b * NS + s) * NT + t;
    const int idx = g_idx[gi];
    const float sim = g_sims[gi];
    idxv[t] = idx;

    const float* yrow = g_yt + ((size_t)b * NHW + idx) * MTOT + h * NDH;
    float q[NDH];
#pragma unroll
    for (int j = 0; j < 8; j++) {
        float4 qv = *(const float4*)(yrow + j * 4);
        q[j * 4 + 0] = qv.x; q[j * 4 + 1] = qv.y; q[j * 4 + 2] = qv.z; q[j * 4 + 3] = qv.w;
        float4 kv = *(const float4*)(yrow + 256 + j * 4);
        *(float4*)&ks[t][j * 4] = kv;
        float4 vv = *(const float4*)(yrow + 512 + j * 4);
        vv.x *= sim; vv.y *= sim; vv.z *= sim; vv.w *= sim;
        *(float4*)&vs[t][j * 4] = vv;
    }
    __syncthreads();

    float mx = -1e30f, l = 0.f;
    float o[NDH];
#pragma unroll
    for (int c = 0; c < NDH; c++) o[c] = 0.f;

    for (int u0 = 0; u0 < NT; u0 += 16) {
        float sc[16];
        float cm = -1e30f;
#pragma unroll
        for (int j = 0; j < 16; j++) {
            float acc = 0.f;
#pragma unroll
            for (int c = 0; c < NDH; c += 4) {
                float4 kv = *(const float4*)&ks[u0 + j][c];
                acc += q[c] * kv.x + q[c + 1] * kv.y + q[c + 2] * kv.z + q[c + 3] * kv.w;
            }
            sc[j] = acc * ATT_SCALE;
            cm = fmaxf(cm, sc[j]);
        }
        float mn = fmaxf(mx, cm);
        float corr = __expf(mx - mn);
        l *= corr;
#pragma unroll
        for (int c = 0; c < NDH; c++) o[c] *= corr;
#pragma unroll
        for (int j = 0; j < 16; j++) {
            float p = __expf(sc[j] - mn);
            l += p;
#pragma unroll
            for (int c = 0; c < NDH; c += 4) {
                float4 vv = *(const float4*)&vs[u0 + j][c];
                o[c + 0] += p * vv.x; o[c + 1] += p * vv.y;
                o[c + 2] += p * vv.z; o[c + 3] += p * vv.w;
            }
        }
        mx = mn;
    }

    const float wscale = sim / l;   // softmax normalize * sims[t]
    __syncthreads();                // everyone done reading ks
#pragma unroll
    for (int c = 0; c < NDH; c++) ks[t][c] = o[c] * wscale;   // reuse ks as out staging
    __syncthreads();

    // coalesced scatter: each warp handles one t-row (32 consecutive floats)
    const int lane = t & 31, wrp = t >> 5;
    for (int r = 0; r < 32; r++) {
        int tt = r * 4 + wrp;
        float val = ks[tt][lane];
        atomicAdd(&g_acc[((size_t)b * NHW + idxv[tt]) * NC + h * NDH + lane], val);
    }
}

// =====================================================================
// Kernel 5: transpose accumulator (B, HW, C) -> out (B, C, HW)
// =====================================================================
__global__ void __launch_bounds__(256) transpose_kernel(float* __restrict__ out) {
    __shared__ float tile[32][33];
    const int b  = blockIdx.z;
    const int n0 = blockIdx.x * 32;
    const int c0 = blockIdx.y * 32;
    const int tx = threadIdx.x, ty = threadIdx.y;
#pragma unroll
    for (int j = 0; j < 32; j += 8)
        tile[ty + j][tx] = g_acc[((size_t)b * NHW + n0 + ty + j) * NC + c0 + tx];
    __syncthreads();
#pragma unroll
    for (int j = 0; j < 32; j += 8)
        out[((size_t)b * NC + c0 + ty + j) * NHW + n0 + tx] = tile[tx][ty + j];
}

// =====================================================================
extern "C" void kernel_launch(void* const* d_in, const int* in_sizes, int n_in,
                              void* d_out, int out_size) {
    const float* x    = (const float*)d_in[0];
    const float* aff  = (const float*)d_in[1];
    const float* lnw  = (const float*)d_in[2];
    const float* lnb  = (const float*)d_in[3];
    const float* wq   = (const float*)d_in[4];
    const float* wk   = (const float*)d_in[5];
    const float* wv   = (const float*)d_in[6];
    float* out = (float*)d_out;

    ln_kernel<<<(NB * NHW) / 256, 256>>>(x, lnw, lnb);
    topk_kernel<<<NB * NS, 256>>>(aff);
    gemm_kernel<<<dim3(NHW / GBN, MTOT / GBM, NB), 256>>>(wq, wk, wv);
    attn_kernel<<<dim3(NS, NHEADS, NB), 128>>>();
    transpose_kernel<<<dim3(NHW / 32, NC / 32, NB), dim3(32, 8)>>>(out);
}